// round 11
// baseline (speedup 1.0000x reference)
#include <cuda_runtime.h>
#include <cuda_bf16.h>
#include <math.h>
#include <stdint.h>

// DeepFM fused inference — bf16 m16n8k16 (round-6 mapping) + Q-GEMM
// eliminated algebraically: mean_j(x^2 K^2)_j == (1/128) * sum_k x_k^2 s_k,
// s_k = sum_j K_kj^2 precomputed in fp32.
// Per CTA: 64 rows, 8 warps = 2 row-groups(32) x 4 n-quarters.

#define HASH_BINS 100000
#define M_TILE 64
#define NTHREADS 256

// Activation smem strides in 32-bit WORDS (2 bf16 per word).
// stride % 8 == 4 -> conflict-free A-fragment LDS and epilogue STS.
#define W128 68
#define W208 108
#define W256 132
#define F128 132   // fp32 stride for final activation buffer

// ---------------- packed weight scratch (device globals) -------------------
// word[(((kt*NP + np)*32 + lane)*4 + t*2 + s)]
//   tile nt = np*2 + t, n = nt*8 + lane/4, k = kt*16 + s*8 + 2*(lane%4) (+1)
__device__ uint32_t g_Kp [ 8 *  8 * 128];   // cross_k    K=128 N=128
__device__ uint32_t g_W1p[ 8 * 13 * 128];   // W1 128->208
__device__ uint32_t g_W2p[13 * 16 * 128];   // W2 208->256
__device__ uint32_t g_W3p[16 * 13 * 128];   // W3 256->208
__device__ uint32_t g_W4p[13 *  8 * 128];   // W4 208->128
__device__ float    g_b1p[208];
__device__ float    g_b2p[256];
__device__ float    g_b3p[208];
__device__ float    g_b4p[128];
__device__ float    g_ksq[128];             // s_k = sum_j cross_k[k][j]^2 (fp32)

__device__ __forceinline__ uint32_t pack_bf2(float lo, float hi) {
    __nv_bfloat162 h = __floats2bfloat162_rn(lo, hi);
    return *reinterpret_cast<uint32_t*>(&h);
}
__device__ __forceinline__ float2 unpack_bf2(uint32_t w) {
    __nv_bfloat162 h = *reinterpret_cast<__nv_bfloat162*>(&w);
    return __bfloat1622float2(h);
}

__device__ __forceinline__ void mma_bf16(float d[4],
                                         uint32_t a0, uint32_t a1, uint32_t a2, uint32_t a3,
                                         uint32_t b0, uint32_t b1) {
    asm volatile(
        "mma.sync.aligned.m16n8k16.row.col.f32.bf16.bf16.f32 "
        "{%0,%1,%2,%3}, {%4,%5,%6,%7}, {%8,%9}, {%0,%1,%2,%3};\n"
        : "+f"(d[0]), "+f"(d[1]), "+f"(d[2]), "+f"(d[3])
        : "r"(a0), "r"(a1), "r"(a2), "r"(a3), "r"(b0), "r"(b1));
}

// ---------------- prep kernel ---------------------------------------------
__device__ __forceinline__ void pack_w(uint32_t* dst, const float* __restrict__ src,
                                       int K_real, int N_real, int NP, int idx) {
    const int j    = idx & 3;
    const int lane = (idx >> 2) & 31;
    const int tp   = idx >> 7;
    const int np   = tp % NP;
    const int kt   = tp / NP;
    const int t = j >> 1, s = j & 1;
    const int n  = (np * 2 + t) * 8 + (lane >> 2);
    const int k0 = kt * 16 + s * 8 + 2 * (lane & 3);
    float v0 = (k0     < K_real && n < N_real) ? src[(size_t)k0 * N_real + n]       : 0.0f;
    float v1 = (k0 + 1 < K_real && n < N_real) ? src[(size_t)(k0 + 1) * N_real + n] : 0.0f;
    dst[idx] = pack_bf2(v0, v1);
}

#define SZ_KP  (8 * 8 * 128)
#define SZ_W1  (8 * 13 * 128)
#define SZ_W2  (13 * 16 * 128)
#define SZ_W3  (16 * 13 * 128)
#define SZ_W4  (13 * 8 * 128)

__global__ void pack_kernel(const float* __restrict__ cross_k,
                            const float* __restrict__ W1, const float* __restrict__ W2,
                            const float* __restrict__ W3, const float* __restrict__ W4,
                            const float* __restrict__ b1, const float* __restrict__ b2,
                            const float* __restrict__ b3, const float* __restrict__ b4) {
    const int i = blockIdx.x * blockDim.x + threadIdx.x;
    const int E0 = SZ_KP, E1 = E0 + SZ_W1, E2 = E1 + SZ_W2, E3 = E2 + SZ_W3;
    const int E4 = E3 + SZ_W4;
    if      (i < E0) pack_w(g_Kp,  cross_k, 128, 128,  8, i);
    else if (i < E1) pack_w(g_W1p, W1,      128, 200, 13, i - E0);
    else if (i < E2) pack_w(g_W2p, W2,      200, 256, 16, i - E1);
    else if (i < E3) pack_w(g_W3p, W3,      256, 200, 13, i - E2);
    else if (i < E4) pack_w(g_W4p, W4,      200, 128,  8, i - E3);
    else {
        int j = i - E4;
        if      (j < 208) g_b1p[j]       = (j < 200) ? b1[j] : 0.0f;
        else if (j < 464) g_b2p[j - 208] = b2[j - 208];
        else if (j < 672) g_b3p[j - 464] = (j - 464 < 200) ? b3[j - 464] : 0.0f;
        else if (j < 800) g_b4p[j - 672] = b4[j - 672];
        else if (j < 928) {
            const int k = j - 800;
            float s = 0.0f;
            for (int n = 0; n < 128; n++) {
                const float v = cross_k[(size_t)k * 128 + n];
                s += v * v;
            }
            g_ksq[k] = s;
        }
    }
}
#define PACK_TOTAL (SZ_KP + SZ_W1 + SZ_W2 + SZ_W3 + SZ_W4 + 928)

// ---------------- GEMM chunk: 32 rows (2 m-groups) x NPAIR pairs ----------
template<int NPAIR, bool F32OUT>
__device__ __forceinline__ void gemm_chunk(
    const uint32_t* __restrict__ Xw, int xs,
    void* __restrict__ Yout, int ys,
    const uint32_t* __restrict__ Wp, const float* __restrict__ biasp,
    int KT, int NP, int row0, int np0, int lane)
{
    const int NT = NPAIR * 2;
    float acc[NT][2][4];
#pragma unroll
    for (int t = 0; t < NT; t++)
#pragma unroll
        for (int mg = 0; mg < 2; mg++)
            acc[t][mg][0] = acc[t][mg][1] = acc[t][mg][2] = acc[t][mg][3] = 0.0f;

    const int gid = lane >> 2, tig = lane & 3;
    const uint32_t* xr[2][2];
#pragma unroll
    for (int mg = 0; mg < 2; mg++) {
        xr[mg][0] = Xw + (row0 + mg * 16 + gid)     * xs;
        xr[mg][1] = Xw + (row0 + mg * 16 + gid + 8) * xs;
    }

    for (int kt = 0; kt < KT; kt++) {
        const int wd = kt * 8 + tig;
        uint32_t a[2][4];
#pragma unroll
        for (int mg = 0; mg < 2; mg++) {
            a[mg][0] = xr[mg][0][wd];
            a[mg][1] = xr[mg][1][wd];
            a[mg][2] = xr[mg][0][wd + 4];
            a[mg][3] = xr[mg][1][wd + 4];
        }
        const uint4* bp = reinterpret_cast<const uint4*>(Wp + (((size_t)kt * NP + np0) * 32 + lane) * 4);
#pragma unroll
        for (int p = 0; p < NPAIR; p++) {
            const uint4 B = bp[p * 32];
#pragma unroll
            for (int mg = 0; mg < 2; mg++) {
                mma_bf16(acc[p * 2][mg],     a[mg][0], a[mg][1], a[mg][2], a[mg][3], B.x, B.y);
                mma_bf16(acc[p * 2 + 1][mg], a[mg][0], a[mg][1], a[mg][2], a[mg][3], B.z, B.w);
            }
        }
    }
#pragma unroll
    for (int t = 0; t < NT; t++) {
        const int nt  = np0 * 2 + t;
        const int col = nt * 8 + 2 * tig;
        const float bc0 = biasp[col], bc1 = biasp[col + 1];
#pragma unroll
        for (int mg = 0; mg < 2; mg++) {
            const int rbase = row0 + mg * 16;
            float v0 = fmaxf(acc[t][mg][0] + bc0, 0.0f);
            float v1 = fmaxf(acc[t][mg][1] + bc1, 0.0f);
            float v2 = fmaxf(acc[t][mg][2] + bc0, 0.0f);
            float v3 = fmaxf(acc[t][mg][3] + bc1, 0.0f);
            if (F32OUT) {
                float* Y = reinterpret_cast<float*>(Yout);
                Y[(rbase + gid)     * ys + col]     = v0;
                Y[(rbase + gid)     * ys + col + 1] = v1;
                Y[(rbase + gid + 8) * ys + col]     = v2;
                Y[(rbase + gid + 8) * ys + col + 1] = v3;
            } else {
                uint32_t* Y = reinterpret_cast<uint32_t*>(Yout);
                Y[(rbase + gid)     * ys + nt * 4 + tig] = pack_bf2(v0, v1);
                Y[(rbase + gid + 8) * ys + nt * 4 + tig] = pack_bf2(v2, v3);
            }
        }
    }
}

template<bool F32OUT>
__device__ __forceinline__ void gemm_range(
    const uint32_t* __restrict__ Xw, int xs, void* __restrict__ Yout, int ys,
    const uint32_t* __restrict__ Wp, const float* __restrict__ biasp,
    int KT, int NP, int row0, int np_begin, int np_end, int lane)
{
    int np = np_begin;
    int rem = np_end - np;
    while (rem >= 4) {
        gemm_chunk<4, F32OUT>(Xw, xs, Yout, ys, Wp, biasp, KT, NP, row0, np, lane);
        np += 4; rem -= 4;
    }
    if (rem == 3)      gemm_chunk<3, F32OUT>(Xw, xs, Yout, ys, Wp, biasp, KT, NP, row0, np, lane);
    else if (rem == 2) gemm_chunk<2, F32OUT>(Xw, xs, Yout, ys, Wp, biasp, KT, NP, row0, np, lane);
    else if (rem == 1) gemm_chunk<1, F32OUT>(Xw, xs, Yout, ys, Wp, biasp, KT, NP, row0, np, lane);
}

// ---------------- FM cross: one pair (2 tiles) x 32 rows, P only ----------
__device__ __forceinline__ void cross_pair(
    const uint32_t* __restrict__ X0,
    int row0, int np0, int lane, float s[4])
{
    float p[2][2][4];
#pragma unroll
    for (int t = 0; t < 2; t++)
#pragma unroll
        for (int mg = 0; mg < 2; mg++)
            p[t][mg][0] = p[t][mg][1] = p[t][mg][2] = p[t][mg][3] = 0.0f;

    const int gid = lane >> 2, tig = lane & 3;
    const uint32_t* xr[2][2];
#pragma unroll
    for (int mg = 0; mg < 2; mg++) {
        xr[mg][0] = X0 + (row0 + mg * 16 + gid)     * W128;
        xr[mg][1] = X0 + (row0 + mg * 16 + gid + 8) * W128;
    }
    for (int kt = 0; kt < 8; kt++) {
        const int wd = kt * 8 + tig;
        const uint4 B1 = *reinterpret_cast<const uint4*>(g_Kp + (((size_t)kt * 8 + np0) * 32 + lane) * 4);
#pragma unroll
        for (int mg = 0; mg < 2; mg++) {
            const uint32_t a0 = xr[mg][0][wd], a1 = xr[mg][1][wd];
            const uint32_t a2 = xr[mg][0][wd + 4], a3 = xr[mg][1][wd + 4];
            mma_bf16(p[0][mg], a0, a1, a2, a3, B1.x, B1.y);
            mma_bf16(p[1][mg], a0, a1, a2, a3, B1.z, B1.w);
        }
    }
#pragma unroll
    for (int t = 0; t < 2; t++)
#pragma unroll
        for (int mg = 0; mg < 2; mg++) {
            s[mg * 2]     += p[t][mg][0] * p[t][mg][0] + p[t][mg][1] * p[t][mg][1];
            s[mg * 2 + 1] += p[t][mg][2] * p[t][mg][2] + p[t][mg][3] * p[t][mg][3];
        }
}

// ---------------- main kernel ---------------------------------------------
__global__ __launch_bounds__(NTHREADS, 2)
void dfm_bf16_kernel(
    const int* __restrict__ user_idx, const int* __restrict__ item_idx,
    const float* __restrict__ user_emb, const float* __restrict__ item_emb,
    const float* __restrict__ lin_w, const float* __restrict__ lin_b,
    const float* __restrict__ W5, const float* __restrict__ b5,
    float* __restrict__ out)
{
    extern __shared__ uint32_t smem[];
    // arenaA: X0 [64][W128]   (4352 w)
    // arenaB: ping [64][W208] (6912 w)  L1 out; reused as L3 out
    // arenaC: pong [64][W256] (8448 w)  L2 out; reused as X4 fp32 [64][F128]
    uint32_t* arenaA = smem;
    uint32_t* arenaB = arenaA + M_TILE * W128;
    uint32_t* arenaC = arenaB + M_TILE * W208;
    float*    rowacc = reinterpret_cast<float*>(arenaC + M_TILE * W256);
    float*    s_ksq  = rowacc + M_TILE;

    uint32_t* X0   = arenaA;
    uint32_t* ping = arenaB;
    uint32_t* pong = arenaC;
    float*    X4   = reinterpret_cast<float*>(arenaC);

    const int tid   = threadIdx.x;
    const int lane  = tid & 31;
    const int w     = tid >> 5;
    const int row0  = (w & 1) * 32;     // m-group of 32 rows
    const int nq    = w >> 1;           // n-quarter 0..3
    const int grow0 = blockIdx.x * M_TILE;

    // ---- gather embeddings -> bf16 words; FM linear; stage s_k ----
    for (int i = tid; i < M_TILE * 64; i += NTHREADS) {
        const int r = i >> 6;
        const int wd = i & 63;
        const int g = grow0 + r;
        float2 v;
        if (wd < 32) v = *reinterpret_cast<const float2*>(&user_emb[(size_t)user_idx[g] * 64 + 2 * wd]);
        else         v = *reinterpret_cast<const float2*>(&item_emb[(size_t)item_idx[g] * 64 + 2 * (wd - 32)]);
        X0[r * W128 + wd] = pack_bf2(v.x, v.y);
    }
    if (tid < 128) s_ksq[tid] = g_ksq[tid];
    for (int r = tid; r < M_TILE; r += NTHREADS) {
        const int g = grow0 + r;
        rowacc[r] = __ldg(&lin_w[user_idx[g]]) + __ldg(&lin_w[HASH_BINS + item_idx[g]])
                  + __ldg(&lin_b[0]);
    }
    __syncthreads();

    // ---- qterm: rowacc[r] -= (0.5/128) * sum_k x_k^2 s_k  (fp32, no GEMM) ----
    {
        const float sc = 0.5f / 128.0f;
        for (int rr = 0; rr < 8; rr++) {
            const int r = w * 8 + rr;
            const float2 v1 = unpack_bf2(X0[r * W128 + lane]);
            const float2 v2 = unpack_bf2(X0[r * W128 + lane + 32]);
            float q = v1.x * v1.x * s_ksq[2 * lane]
                    + v1.y * v1.y * s_ksq[2 * lane + 1]
                    + v2.x * v2.x * s_ksq[2 * lane + 64]
                    + v2.y * v2.y * s_ksq[2 * lane + 65];
            q += __shfl_xor_sync(0xffffffffu, q, 16);
            q += __shfl_xor_sync(0xffffffffu, q, 8);
            q += __shfl_xor_sync(0xffffffffu, q, 4);
            q += __shfl_xor_sync(0xffffffffu, q, 2);
            q += __shfl_xor_sync(0xffffffffu, q, 1);
            if (lane == 0) atomicAdd(&rowacc[r], -sc * q);
        }
    }

    // ---- FM cross P term: 8 pairs, 2 per n-quarter ----
    {
        float s[4] = {0.0f, 0.0f, 0.0f, 0.0f};
        cross_pair(X0, row0, 2 * nq,     lane, s);
        cross_pair(X0, row0, 2 * nq + 1, lane, s);
#pragma unroll
        for (int i = 0; i < 4; i++) {
            s[i] += __shfl_xor_sync(0xffffffffu, s[i], 1);
            s[i] += __shfl_xor_sync(0xffffffffu, s[i], 2);
        }
        if ((lane & 3) == 0) {
            const int gid = lane >> 2;
            const float sc = 0.5f / 128.0f;
            atomicAdd(&rowacc[row0 + gid],          sc * s[0]);
            atomicAdd(&rowacc[row0 + gid + 8],      sc * s[1]);
            atomicAdd(&rowacc[row0 + 16 + gid],     sc * s[2]);
            atomicAdd(&rowacc[row0 + 16 + gid + 8], sc * s[3]);
        }
    }

    // ---- L1: 128 -> 208, X0 -> ping.  Pairs: 4/3/3/3 per quarter ----
    {
        const int begin = (nq == 0) ? 0 : (4 + 3 * (nq - 1));
        const int end   = begin + ((nq == 0) ? 4 : 3);
        gemm_range<false>(X0, W128, ping, W208, g_W1p, g_b1p, 8, 13, row0, begin, end, lane);
    }
    __syncthreads();

    // ---- L2: 208 -> 256, ping -> pong.  4 pairs per quarter ----
    gemm_range<false>(ping, W208, pong, W256, g_W2p, g_b2p, 13, 16, row0, 4 * nq, 4 * nq + 4, lane);
    __syncthreads();

    // ---- L3: 256 -> 208, pong -> ping (ping dead after L2) ----
    {
        const int begin = (nq == 0) ? 0 : (4 + 3 * (nq - 1));
        const int end   = begin + ((nq == 0) ? 4 : 3);
        gemm_range<false>(pong, W256, ping, W208, g_W3p, g_b3p, 16, 13, row0, begin, end, lane);
    }
    __syncthreads();

    // ---- L4: 208 -> 128, ping -> X4 (fp32, arenaC; pong dead).  2 pairs ----
    gemm_range<true>(ping, W208, X4, F128, g_W4p, g_b4p, 13, 8, row0, 2 * nq, 2 * nq + 2, lane);
    __syncthreads();

    // ---- L5: Dense(1) + linear + cross + sigmoid ----
    if (tid < M_TILE) {
        const int r = tid;
        float acc = __ldg(&b5[0]);
#pragma unroll 8
        for (int k = 0; k < 128; k++)
            acc = fmaf(X4[r * F128 + k], __ldg(&W5[k]), acc);
        const float logit = acc + rowacc[r];
        out[grow0 + r] = 1.0f / (1.0f + expf(-logit));
    }
}

extern "C" void kernel_launch(void* const* d_in, const int* in_sizes, int n_in,
                              void* d_out, int out_size)
{
    const int*   user_idx = (const int*)d_in[0];
    const int*   item_idx = (const int*)d_in[1];
    const float* user_emb = (const float*)d_in[2];
    const float* item_emb = (const float*)d_in[3];
    const float* lin_w    = (const float*)d_in[4];
    const float* lin_b    = (const float*)d_in[5];
    const float* cross_k  = (const float*)d_in[6];
    const float* W1 = (const float*)d_in[7];  const float* b1 = (const float*)d_in[8];
    const float* W2 = (const float*)d_in[9];  const float* b2 = (const float*)d_in[10];
    const float* W3 = (const float*)d_in[11]; const float* b3 = (const float*)d_in[12];
    const float* W4 = (const float*)d_in[13]; const float* b4 = (const float*)d_in[14];
    const float* W5 = (const float*)d_in[15]; const float* b5 = (const float*)d_in[16];
    float* out = (float*)d_out;

    const int B = in_sizes[0];

    pack_kernel<<<(PACK_TOTAL + 255) / 256, 256>>>(cross_k, W1, W2, W3, W4, b1, b2, b3, b4);

    const int smem_words = M_TILE * W128 + M_TILE * W208 + M_TILE * W256 + M_TILE + 128;
    const int smem_bytes = smem_words * 4;   // ~78 KB

    cudaFuncSetAttribute(dfm_bf16_kernel, cudaFuncAttributeMaxDynamicSharedMemorySize, smem_bytes);

    dfm_bf16_kernel<<<B / M_TILE, NTHREADS, smem_bytes>>>(
        user_idx, item_idx, user_emb, item_emb, lin_w, lin_b, W5, b5, out);
}